// round 16
// baseline (speedup 1.0000x reference)
#include <cuda_runtime.h>
#include <cuda_fp16.h>
#include <cstdint>

#define NLAYERS 25
#define KOUT 50
#define FW 1266
#define ROWS 64
#define THREADS 512
#define MAXPAIR 38                       // k16-pairs per layer (76 ks)
#define NT 7
#define RSE 1272                         // fp16 elems/row (2544B, 16B-aligned)
#define A_BYTES (ROWS * RSE * 2)         // 162816
#define WOFF A_BYTES
#define PB 3584                          // per-pair W block: 7 nt * 32 lanes * 16B
#define CK 16                            // ks per chunk (= 8 pairs)
#define CPAIR 8
#define WBUF (CPAIR * PB)                // 28672
#define SMEM_TOTAL (WOFF + 2 * WBUF)     // 220160

// W fragments: [layer][pair(38)][tile(7)][lane(32)][word(4)]
// word = {ks0_r0, ks0_r1, ks1_r0, ks1_r1} -> one LDS.128 feeds 4 MMAs
#define WFRAG_WORDS (NLAYERS * MAXPAIR * NT * 32 * 4)   // 851,200 (3.4 MB)
__device__ uint32_t g_wfrag[WFRAG_WORDS];

__device__ __forceinline__ uint32_t packh2(__half a, __half b) {
    return (uint32_t)__half_as_ushort(a) | ((uint32_t)__half_as_ushort(b) << 16);
}

// ---- prekernel: fp32 W -> ks-pair fragment quads ----
__global__ void stage_w_kernel(const float* __restrict__ Ws) {
    int i = blockIdx.x * blockDim.x + threadIdx.x;
    if (i >= WFRAG_WORDS) return;
    int w = i;
    int word = w & 3;   w >>= 2;
    int ln   = w & 31;  w >>= 5;
    int tile = w % NT;  w /= NT;
    int pair = w % MAXPAIR;
    int layer = w / MAXPAIR;
    int n  = tile * 8 + (ln >> 2);
    int ks = pair * 2 + (word >> 1);
    int reg = word & 1;
    int k = ks * 16 + ((ln & 3) << 1) + reg * 8;   // k <= 1214, in-bounds
    float w0 = 0.f, w1 = 0.f;
    if (n < KOUT) {
        const float* p = Ws + ((size_t)layer * KOUT + n) * FW + k;
        w0 = p[0]; w1 = p[1];
    }
    g_wfrag[i] = packh2(__float2half_rn(w0), __float2half_rn(w1));
}

#define MMA(d, a, b0_, b1_) \
    asm volatile("mma.sync.aligned.m16n8k16.row.col.f32.f16.f16.f32 " \
        "{%0,%1,%2,%3},{%4,%5,%6,%7},{%8,%9},{%0,%1,%2,%3};" \
        : "+f"(d[0]), "+f"(d[1]), "+f"(d[2]), "+f"(d[3]) \
        : "r"(a[0]), "r"(a[1]), "r"(a[2]), "r"(a[3]), "r"(b0_), "r"(b1_))

#define LDSM4(r, addr) \
    asm volatile("ldmatrix.sync.aligned.m8n8.x4.shared.b16 {%0,%1,%2,%3}, [%4];" \
        : "=r"(r[0]), "=r"(r[1]), "=r"(r[2]), "=r"(r[3]) : "r"(addr))

__device__ __forceinline__ void cp16(uint32_t dst, const void* src) {
    asm volatile("cp.async.cg.shared.global [%0], [%1], 16;" :: "r"(dst), "l"(src));
}
__device__ __forceinline__ void barkg(int id) {
    asm volatile("bar.sync %0, 128;" :: "r"(id) : "memory");
}

__global__ void __launch_bounds__(THREADS, 1) value_model_mma_kernel(
    const float* __restrict__ state,
    const float* __restrict__ bs,
    const float* __restrict__ Wout,
    const float* __restrict__ bout,
    float* __restrict__ out)
{
    extern __shared__ char smraw[];
    __half* A = (__half*)smraw;
    const uint32_t sm_u32 = (uint32_t)__cvta_generic_to_shared(smraw);

    const int tid  = threadIdx.x;
    const int lane = tid & 31;
    const int wid  = tid >> 5;
    const int cta  = blockIdx.x;
    const int kg   = wid >> 2;         // 0..3: k-split (2 pairs = 4 ks per chunk)
    const int m    = (wid >> 1) & 1;   // row-half: rows m*32 .. m*32+31
    const int ng   = wid & 1;          // n-group: tiles ng*4 .. (<7)
    const int sub  = wid & 3;          // (m, ng) id
    const int ltid = tid & 127;        // thread within kg group
    const int bid  = kg + 1;           // named barrier id

    // ---- zero A plane (zero tail masks padded-k W garbage) ----
    {
        uint4 z = make_uint4(0u, 0u, 0u, 0u);
        uint4* p = (uint4*)smraw;
        for (int i = tid; i < A_BYTES / 16; i += THREADS) p[i] = z;
    }
    __syncthreads();

    // ---- initial state (64 x 16) ----
    for (int idx = tid; idx < ROWS * 16; idx += THREADS) {
        int r = idx >> 4, j = idx & 15;
        A[r * RSE + j] = __float2half_rn(state[(cta * ROWS + r) * 16 + j]);
    }
    __syncthreads();

    const uint32_t abase = sm_u32 + (uint32_t)((m * 32 + (lane & 15)) * RSE) * 2u
                                  + (uint32_t)(lane >> 4) * 16u;
    const uint32_t wsm = sm_u32 + WOFF;
    float4* scratch4 = (float4*)(smraw + WOFF);   // 48KB overlay on dead W buffers

    const uint32_t sl_off = (uint32_t)(kg * 2) * PB;   // this kg's pair-slice offset

    int width = 16;
    for (int l = 0; l < NLAYERS; l++) {
        const int nks = (width + 15) >> 4;
        const int nc  = (nks + CK - 1) / CK;

        float acc[2][4][4] = {};

        // ---- per-kg prologue: stage this group's pair-slice of chunk 0 ----
        {
            const int ksn0 = (nks < CK) ? nks : CK;
            const int np0 = (ksn0 + 1) >> 1;                     // pairs in chunk 0
            int pcnt = np0 - kg * 2; pcnt = (pcnt < 0) ? 0 : ((pcnt > 2) ? 2 : pcnt);
            const char* src = (const char*)g_wfrag
                            + (size_t)(l * MAXPAIR + kg * 2) * PB;
            const int nops = pcnt * 224;
            for (int i = ltid; i < nops; i += 128)
                cp16(wsm + sl_off + i * 16, src + (size_t)i * 16);
            asm volatile("cp.async.commit_group;");
        }

        for (int c = 0; c < nc; c++) {
            // per-kg stage pair-slice of chunk c+1
            if (c + 1 < nc) {
                const int rem = nks - (c + 1) * CK;
                const int ksn1 = (rem < CK) ? rem : CK;
                const int np1 = (ksn1 + 1) >> 1;
                int pcnt = np1 - kg * 2; pcnt = (pcnt < 0) ? 0 : ((pcnt > 2) ? 2 : pcnt);
                const char* src = (const char*)g_wfrag
                                + (size_t)(l * MAXPAIR + (c + 1) * CPAIR + kg * 2) * PB;
                uint32_t dst = wsm + (((c + 1) & 1) ? WBUF : 0) + sl_off;
                const int nops = pcnt * 224;
                for (int i = ltid; i < nops; i += 128)
                    cp16(dst + i * 16, src + (size_t)i * 16);
                asm volatile("cp.async.commit_group;");
                asm volatile("cp.async.wait_group 1;");
            } else {
                asm volatile("cp.async.wait_group 0;");
            }
            barkg(bid);    // publish slice c within this kg group

            const uint32_t* wb = (const uint32_t*)(smraw + WOFF + ((c & 1) ? WBUF : 0));
            const int ksn = min(CK, nks - c * CK);
            const int npair = (ksn + 1) >> 1;

            #pragma unroll
            for (int p = 0; p < 2; p++) {
                const int pairl = kg * 2 + p;      // pair index within chunk
                if (pairl < npair) {
                    const int ks0 = c * CK + pairl * 2;
                    uint32_t a00[4], a10[4], a01[4], a11[4];
                    const uint32_t ad = abase + (uint32_t)ks0 * 32u;
                    LDSM4(a00, ad);
                    LDSM4(a10, ad + 16u * RSE * 2u);
                    LDSM4(a01, ad + 32u);
                    LDSM4(a11, ad + 32u + 16u * RSE * 2u);
                    const uint32_t* wk = wb + pairl * 896;   // PB/4 words
                    #pragma unroll
                    for (int t = 0; t < 4; t++) {
                        const int tile = ng * 4 + t;
                        if (tile < NT) {
                            const uint4 b = *(const uint4*)(wk + tile * 128 + lane * 4);
                            MMA(acc[0][t], a00, b.x, b.y);
                            MMA(acc[1][t], a10, b.x, b.y);
                            MMA(acc[0][t], a01, b.z, b.w);
                            MMA(acc[1][t], a11, b.z, b.w);
                        }
                    }
                }
            }
            barkg(bid);    // this group's reads of slice c done (frees it for c+2)
        }

        // ---- epilogue (full-CTA): single-wave kg-reduction, bias + leaky, append ----
        __syncthreads();
        if (kg != 0) {
            float4* slot = scratch4 + ((kg - 1) * 4 + sub) * 256;
            #pragma unroll
            for (int mt = 0; mt < 2; mt++)
                #pragma unroll
                for (int t = 0; t < 4; t++)
                    slot[(mt * 4 + t) * 32 + lane] =
                        make_float4(acc[mt][t][0], acc[mt][t][1],
                                    acc[mt][t][2], acc[mt][t][3]);
        }
        __syncthreads();
        if (kg == 0) {
            #pragma unroll
            for (int q = 0; q < 3; q++) {
                const float4* slot = scratch4 + (q * 4 + sub) * 256;
                #pragma unroll
                for (int mt = 0; mt < 2; mt++)
                    #pragma unroll
                    for (int t = 0; t < 4; t++) {
                        float4 v = slot[(mt * 4 + t) * 32 + lane];
                        acc[mt][t][0] += v.x; acc[mt][t][1] += v.y;
                        acc[mt][t][2] += v.z; acc[mt][t][3] += v.w;
                    }
            }
            #pragma unroll
            for (int mt = 0; mt < 2; mt++)
                #pragma unroll
                for (int t = 0; t < 4; t++) {
                    const int tile = ng * 4 + t;
                    if (tile < NT) {
                        const int n0 = tile * 8 + ((lane & 3) << 1);
                        const int rbase = m * 32 + mt * 16 + (lane >> 2);
                        #pragma unroll
                        for (int half = 0; half < 2; half++) {
                            const int n = n0 + half;
                            if (n < KOUT) {
                                const float bz = bs[l * KOUT + n];
                                #pragma unroll
                                for (int rr = 0; rr < 2; rr++) {
                                    float y = acc[mt][t][rr * 2 + half] + bz;
                                    y = (y > 0.f) ? y : 0.01f * y;
                                    A[(rbase + rr * 8) * RSE + width + n] =
                                        __float2half_rn(y);
                                }
                            }
                        }
                    }
                }
        }
        width += KOUT;
        __syncthreads();
    }

    // ---- final projection: out[r] = x . Wout + bout ----
    #pragma unroll
    for (int t = 0; t < 4; t++) {
        const int r = wid * 4 + t;
        float s = 0.f;
        for (int j = lane; j < FW; j += 32)
            s += __half2float(A[r * RSE + j]) * Wout[j];
        #pragma unroll
        for (int o = 16; o; o >>= 1) s += __shfl_xor_sync(0xffffffffu, s, o);
        if (lane == 0) out[cta * ROWS + r] = s + bout[0];
    }
}

extern "C" void kernel_launch(void* const* d_in, const int* in_sizes, int n_in,
                              void* d_out, int out_size) {
    const float* state = (const float*)d_in[0];
    const float* Ws    = (const float*)d_in[1];
    const float* bs    = (const float*)d_in[2];
    const float* Wout  = (const float*)d_in[3];
    const float* bout  = (const float*)d_in[4];
    float* out = (float*)d_out;

    const int B = in_sizes[0] / 16;   // 32768

    stage_w_kernel<<<(WFRAG_WORDS + 255) / 256, 256>>>(Ws);

    cudaFuncSetAttribute(value_model_mma_kernel,
                         cudaFuncAttributeMaxDynamicSharedMemorySize, SMEM_TOTAL);
    value_model_mma_kernel<<<B / ROWS, THREADS, SMEM_TOTAL>>>(state, bs, Wout, bout, out);
}

// round 17
// speedup vs baseline: 1.0597x; 1.0597x over previous
#include <cuda_runtime.h>
#include <cuda_fp16.h>
#include <cstdint>

#define NLAYERS 25
#define KOUT 50
#define FW 1266
#define ROWS 64
#define THREADS 512
#define MAXKS 76
#define NT 7
#define RSE 1272                         // fp16 elems/row (2544B, 16B-aligned)
#define A_BYTES (ROWS * RSE * 2)         // 162816
#define WOFF A_BYTES
#define KSB 1792                         // per-ks W block: 7 nt * 32 lanes * 8B
#define CK 16                            // ks per chunk
#define WBUF (CK * KSB)                  // 28672
#define SMEM_TOTAL (WOFF + 2 * WBUF)     // 220160

// W fragments: [layer][ks(76)][nt(7)][lane(32)][word(2)]; word = {bhi_r0, bhi_r1}
#define WFRAG_WORDS (NLAYERS * MAXKS * NT * 32 * 2)   // 851,200 (3.4 MB)
__device__ uint32_t g_wfrag[WFRAG_WORDS];

__device__ __forceinline__ uint32_t packh2(__half a, __half b) {
    return (uint32_t)__half_as_ushort(a) | ((uint32_t)__half_as_ushort(b) << 16);
}

// ---- prekernel: fp32 W -> fragment-ordered fp16 pairs (identical to R10/R15) ----
__global__ void stage_w_kernel(const float* __restrict__ Ws) {
    int i = blockIdx.x * blockDim.x + threadIdx.x;
    if (i >= WFRAG_WORDS) return;
    int w = i;
    int reg  = w & 1;  w >>= 1;
    int ln   = w & 31; w >>= 5;
    int nt   = w % NT; w /= NT;
    int ks   = w % MAXKS;
    int layer = w / MAXKS;
    int n = nt * 8 + (ln >> 2);
    int k = ks * 16 + ((ln & 3) << 1) + reg * 8;   // k <= 1214, in-bounds
    float w0 = 0.f, w1 = 0.f;
    if (n < KOUT) {
        const float* p = Ws + ((size_t)layer * KOUT + n) * FW + k;
        w0 = p[0]; w1 = p[1];
    }
    g_wfrag[i] = packh2(__float2half_rn(w0), __float2half_rn(w1));
}

#define MMA(d, a, b0_, b1_) \
    asm volatile("mma.sync.aligned.m16n8k16.row.col.f32.f16.f16.f32 " \
        "{%0,%1,%2,%3},{%4,%5,%6,%7},{%8,%9},{%0,%1,%2,%3};" \
        : "+f"(d[0]), "+f"(d[1]), "+f"(d[2]), "+f"(d[3]) \
        : "r"(a[0]), "r"(a[1]), "r"(a[2]), "r"(a[3]), "r"(b0_), "r"(b1_))

#define LDSM4(r, addr) \
    asm volatile("ldmatrix.sync.aligned.m8n8.x4.shared.b16 {%0,%1,%2,%3}, [%4];" \
        : "=r"(r[0]), "=r"(r[1]), "=r"(r[2]), "=r"(r[3]) : "r"(addr))

__device__ __forceinline__ void cp16(uint32_t dst, const void* src) {
    asm volatile("cp.async.cg.shared.global [%0], [%1], 16;" :: "r"(dst), "l"(src));
}
__device__ __forceinline__ void barkg(int id) {
    asm volatile("bar.sync %0, 128;" :: "r"(id) : "memory");
}

__global__ void __launch_bounds__(THREADS, 1) value_model_mma_kernel(
    const float* __restrict__ state,
    const float* __restrict__ bs,
    const float* __restrict__ Wout,
    const float* __restrict__ bout,
    float* __restrict__ out)
{
    extern __shared__ char smraw[];
    __half* A = (__half*)smraw;
    const uint32_t sm_u32 = (uint32_t)__cvta_generic_to_shared(smraw);

    const int tid  = threadIdx.x;
    const int lane = tid & 31;
    const int wid  = tid >> 5;
    const int cta  = blockIdx.x;
    const int kg   = wid >> 2;         // 0..3: k-split within 16-ks chunk (4 ks each)
    const int m    = (wid >> 1) & 1;   // row-half: rows m*32 .. m*32+31
    const int ng   = wid & 1;          // n-group: tiles ng*4 .. (<7)
    const int ltid = tid & 127;        // thread within kg group (warps contiguous)
    const int bid  = kg + 1;           // named barrier id for this kg group

    // ---- zero A plane ----
    {
        uint4 z = make_uint4(0u, 0u, 0u, 0u);
        uint4* p = (uint4*)smraw;
        for (int i = tid; i < A_BYTES / 16; i += THREADS) p[i] = z;
    }
    __syncthreads();

    // ---- initial state (64 x 16) ----
    for (int idx = tid; idx < ROWS * 16; idx += THREADS) {
        int r = idx >> 4, j = idx & 15;
        A[r * RSE + j] = __float2half_rn(state[(cta * ROWS + r) * 16 + j]);
    }
    __syncthreads();

    // ldmatrix base for this warp's two m16 tiles (rows m*32 and m*32+16)
    const uint32_t abase = sm_u32 + (uint32_t)((m * 32 + (lane & 15)) * RSE) * 2u
                                  + (uint32_t)(lane >> 4) * 16u;
    const uint32_t wsm = sm_u32 + WOFF;
    // distributed-epilogue scratch: [kg(4)][m(2)][tile(7)][mt(2)][lane(32)] float4
    //   = 4*2*7*2*32*16 = 57,344 B — exactly overlays BOTH dead W buffers
    float4* scratch4 = (float4*)(smraw + WOFF);

    // this kg group's slice inside a chunk: ksl in [4kg, 4kg+4)
    const uint32_t sl_off = (uint32_t)(kg * 4) * KSB;

    int width = 16;
    for (int l = 0; l < NLAYERS; l++) {
        const int nks = (width + 15) >> 4;
        const int nc  = (nks + CK - 1) / CK;

        float acc[2][4][4] = {};

        // ---- per-kg prologue: stage this group's slice of chunk 0 ----
        {
            const int ksn0 = (nks < CK) ? nks : CK;
            int scnt = ksn0 - kg * 4; scnt = (scnt < 0) ? 0 : ((scnt > 4) ? 4 : scnt);
            const char* src = (const char*)g_wfrag
                            + (size_t)(l * MAXKS + kg * 4) * KSB;
            const int nops = scnt * 112;
            for (int i = ltid; i < nops; i += 128)
                cp16(wsm + sl_off + i * 16, src + (size_t)i * 16);
            asm volatile("cp.async.commit_group;");
        }

        for (int c = 0; c < nc; c++) {
            // per-kg stage slice of chunk c+1
            if (c + 1 < nc) {
                const int rem = nks - (c + 1) * CK;
                const int ksn1 = (rem < CK) ? rem : CK;
                int scnt = ksn1 - kg * 4; scnt = (scnt < 0) ? 0 : ((scnt > 4) ? 4 : scnt);
                const char* src = (const char*)g_wfrag
                                + (size_t)(l * MAXKS + (c + 1) * CK + kg * 4) * KSB;
                uint32_t dst = wsm + (((c + 1) & 1) ? WBUF : 0) + sl_off;
                const int nops = scnt * 112;
                for (int i = ltid; i < nops; i += 128)
                    cp16(dst + i * 16, src + (size_t)i * 16);
                asm volatile("cp.async.commit_group;");
                asm volatile("cp.async.wait_group 1;");
            } else {
                asm volatile("cp.async.wait_group 0;");
            }
            barkg(bid);    // publish slice c within this kg group

            const uint32_t* wb = (const uint32_t*)(smraw + WOFF + ((c & 1) ? WBUF : 0));
            const int ksn = min(CK, nks - c * CK);

            #pragma unroll
            for (int i = 0; i < 4; i++) {
                const int ksl = kg * 4 + i;
                if (ksl < ksn) {
                    const int ks = c * CK + ksl;
                    uint32_t a0[4], a1[4];
                    const uint32_t ad = abase + (uint32_t)ks * 32u;
                    LDSM4(a0, ad);
                    LDSM4(a1, ad + 16u * RSE * 2u);
                    const uint32_t* wk = wb + ksl * 448;
                    #pragma unroll
                    for (int t = 0; t < 4; t++) {
                        const int tile = ng * 4 + t;
                        if (tile < NT) {
                            const uint2 b = *(const uint2*)(wk + tile * 64 + lane * 2);
                            MMA(acc[0][t], a0, b.x, b.y);
                            MMA(acc[1][t], a1, b.x, b.y);
                        }
                    }
                }
            }
            barkg(bid);    // this group's reads of slice c done (frees it for c+2)
        }

        // ---- distributed epilogue ----
        __syncthreads();   // all kg groups done with W buffers (scratch overlays them)
        // (1) every warp publishes its accumulators
        #pragma unroll
        for (int mt = 0; mt < 2; mt++)
            #pragma unroll
            for (int t = 0; t < 4; t++) {
                const int tile = ng * 4 + t;
                if (tile < NT)
                    scratch4[(((kg * 2 + m) * 7 + tile) * 2 + mt) * 32 + lane] =
                        make_float4(acc[mt][t][0], acc[mt][t][1],
                                    acc[mt][t][2], acc[mt][t][3]);
            }
        __syncthreads();
        // (2) all 512 threads reduce + bias + leaky + append (896 slots, <=2 each)
        #pragma unroll
        for (int si = 0; si < 2; si++) {
            const int s = tid + si * THREADS;
            if (s < 896) {
                const int lane_s = s & 31;
                const int mt     = (s >> 5) & 1;
                const int mtile  = s >> 6;          // mm*7 + tile
                const int tile   = mtile % 7;
                const int mm     = mtile / 7;
                const int n0 = tile * 8 + ((lane_s & 3) << 1);
                if (n0 < KOUT) {
                    const int base = ((mm * 7 + tile) * 2 + mt) * 32 + lane_s;
                    float4 v = scratch4[base];                     // kg0
                    #pragma unroll
                    for (int q = 1; q < 4; q++) {                  // + kg1..kg3 (same order as R15)
                        float4 w = scratch4[base + q * (2 * 7 * 2 * 32)];
                        v.x += w.x; v.y += w.y; v.z += w.z; v.w += w.w;
                    }
                    const float b0 = bs[l * KOUT + n0];
                    const float b1 = bs[l * KOUT + n0 + 1];
                    float y00 = v.x + b0, y01 = v.y + b1;          // row rbase
                    float y10 = v.z + b0, y11 = v.w + b1;          // row rbase+8
                    y00 = (y00 > 0.f) ? y00 : 0.01f * y00;
                    y01 = (y01 > 0.f) ? y01 : 0.01f * y01;
                    y10 = (y10 > 0.f) ? y10 : 0.01f * y10;
                    y11 = (y11 > 0.f) ? y11 : 0.01f * y11;
                    const int rbase = mm * 32 + mt * 16 + (lane_s >> 2);
                    const int e0 = rbase * RSE + width + n0;
                    const int e1 = (rbase + 8) * RSE + width + n0;
                    *(uint32_t*)(A + e0) = packh2(__float2half_rn(y00), __float2half_rn(y01));
                    *(uint32_t*)(A + e1) = packh2(__float2half_rn(y10), __float2half_rn(y11));
                }
            }
        }
        width += KOUT;
        __syncthreads();   // A writes + scratch reads done before next prologue
    }

    // ---- final projection: out[r] = x . Wout + bout ----
    #pragma unroll
    for (int t = 0; t < 4; t++) {
        const int r = wid * 4 + t;
        float s = 0.f;
        for (int j = lane; j < FW; j += 32)
            s += __half2float(A[r * RSE + j]) * Wout[j];
        #pragma unroll
        for (int o = 16; o; o >>= 1) s += __shfl_xor_sync(0xffffffffu, s, o);
        if (lane == 0) out[cta * ROWS + r] = s + bout[0];
    }
}

extern "C" void kernel_launch(void* const* d_in, const int* in_sizes, int n_in,
                              void* d_out, int out_size) {
    const float* state = (const float*)d_in[0];
    const float* Ws    = (const float*)d_in[1];
    const float* bs    = (const float*)d_in[2];
    const float* Wout  = (const float*)d_in[3];
    const float* bout  = (const float*)d_in[4];
    float* out = (float*)d_out;

    const int B = in_sizes[0] / 16;   // 32768

    stage_w_kernel<<<(WFRAG_WORDS + 255) / 256, 256>>>(Ws);

    cudaFuncSetAttribute(value_model_mma_kernel,
                         cudaFuncAttributeMaxDynamicSharedMemorySize, SMEM_TOTAL);
    value_model_mma_kernel<<<B / ROWS, THREADS, SMEM_TOTAL>>>(state, bs, Wout, bout, out);
}